// round 16
// baseline (speedup 1.0000x reference)
#include <cuda_runtime.h>
#include <cuda_bf16.h>
#include <cuda_fp16.h>
#include <mma.h>
#include <math.h>
#include <stdint.h>

#define NN 50000
#define NNP 50048         // padded rows for tile-overrun stores
#define NE 800000
#define FIN 64
#define DD 128
#define NL 3
#define NB 8
#define POOL_C 64
#define WTOT 122880       // 128*64 + 3*128*256 + 128*128
#define ASTR 40           // smem leading dim (elems): 32 K + 8 pad

using namespace nvcuda;

// ---------------- scratch (device globals; no allocation) ----------------
__device__ __align__(16) float g_h[NN * DD];
__device__ __align__(16) __half g_hh[NN * DD];       // fp16 copy for gathers
__device__ __align__(16) float g_z[NNP * DD];        // padded
__device__ __align__(16) float g_agg[NN * DD];
__device__ __align__(16) __nv_bfloat16 g_wh[WTOT];   // weights [n][k], bf16 hi
__device__ __align__(16) __nv_bfloat16 g_wl[WTOT];   // bf16 lo
__device__ int   g_cnt[NN];
__device__ int   g_rowptr[NN + 1];
__device__ int   g_cursor[NN];
__device__ int   g_col[NE];
__device__ float g_deg[NN];
__device__ float g_logit[NN];
__device__ float g_red[256];
__device__ float g_consts[2];
__device__ int   g_bstart[NB + 1];
__device__ float g_pool_part[NB * POOL_C * DD];
__device__ float g_pooled[NB * DD];

// ---------------- helpers ----------------
__device__ __forceinline__ float geluf(float x) {
    return 0.5f * x * (1.0f + erff(x * 0.7071067811865476f));
}
__device__ __forceinline__ float wsum(float v) {
#pragma unroll
    for (int o = 16; o > 0; o >>= 1) v += __shfl_xor_sync(0xffffffffu, v, o);
    return v;
}
__device__ __forceinline__ float4 ln128(float4 v, const float* __restrict__ g,
                                        const float* __restrict__ b, int lane) {
    float m = wsum(v.x + v.y + v.z + v.w) * (1.0f / 128.0f);
    float dx = v.x - m, dy = v.y - m, dz = v.z - m, dw = v.w - m;
    float var = wsum(dx * dx + dy * dy + dz * dz + dw * dw) * (1.0f / 128.0f);
    float rs = rsqrtf(var + 1e-5f);
    float4 gg = *reinterpret_cast<const float4*>(g + lane * 4);
    float4 bb = *reinterpret_cast<const float4*>(b + lane * 4);
    return make_float4(dx * rs * gg.x + bb.x, dy * rs * gg.y + bb.y,
                       dz * rs * gg.z + bb.z, dw * rs * gg.w + bb.w);
}
__device__ __forceinline__ void split2(float a, float b, uint32_t& hi, uint32_t& lo) {
    __nv_bfloat16 ha = __float2bfloat16(a), hb = __float2bfloat16(b);
    __nv_bfloat162 th; th.x = ha; th.y = hb;
    hi = *reinterpret_cast<uint32_t*>(&th);
    __nv_bfloat162 tl;
    tl.x = __float2bfloat16(a - __bfloat162float(ha));
    tl.y = __float2bfloat16(b - __bfloat162float(hb));
    lo = *reinterpret_cast<uint32_t*>(&tl);
}
__device__ __forceinline__ void store_h_pair(float4 r, int row, int lane) {
    *reinterpret_cast<float4*>(g_h + (size_t)row * DD + lane * 4) = r;
    __half2 h0 = __floats2half2_rn(r.x, r.y);
    __half2 h1 = __floats2half2_rn(r.z, r.w);
    uint2 hp = make_uint2(*reinterpret_cast<uint32_t*>(&h0),
                          *reinterpret_cast<uint32_t*>(&h1));
    *reinterpret_cast<uint2*>(g_hh + (size_t)row * DD + lane * 4) = hp;
}
__device__ __forceinline__ void acc_h2(float4& a, uint2 v) {
    float2 f0 = __half22float2(*reinterpret_cast<__half2*>(&v.x));
    float2 f1 = __half22float2(*reinterpret_cast<__half2*>(&v.y));
    a.x += f0.x; a.y += f0.y; a.z += f1.x; a.w += f1.y;
}

// ---------------- CSR build ----------------
__global__ void k_zero() {
    int i = blockIdx.x * blockDim.x + threadIdx.x;
    if (i < NN) g_cnt[i] = 0;
}
__global__ void k_count(const int* __restrict__ ei) {
    int e = blockIdx.x * blockDim.x + threadIdx.x;
    if (e < NE) atomicAdd(&g_cnt[ei[NE + e]], 1);
}
__global__ void k_scan() {
    __shared__ int sh_warp[32];
    __shared__ int sh_carry;
    int t = threadIdx.x;
    if (t == 0) { sh_carry = 0; g_rowptr[0] = 0; }
    __syncthreads();
    for (int base = 0; base < NN; base += 1024) {
        int i = base + t;
        int v = (i < NN) ? g_cnt[i] : 0;
        int x = v;
#pragma unroll
        for (int o = 1; o < 32; o <<= 1) {
            int y = __shfl_up_sync(0xffffffffu, x, o);
            if ((t & 31) >= o) x += y;
        }
        if ((t & 31) == 31) sh_warp[t >> 5] = x;
        __syncthreads();
        if (t < 32) {
            int w = sh_warp[t];
#pragma unroll
            for (int o = 1; o < 32; o <<= 1) {
                int y = __shfl_up_sync(0xffffffffu, w, o);
                if (t >= o) w += y;
            }
            sh_warp[t] = w;
        }
        __syncthreads();
        int pre = (t >= 32) ? sh_warp[(t >> 5) - 1] : 0;
        int incl = x + pre + sh_carry;
        if (i < NN) {
            g_rowptr[i + 1] = incl;
            g_cursor[i] = incl - v;
            g_deg[i] = (v > 0) ? (float)v : 1.0f;
        }
        __syncthreads();
        if (t == 1023) sh_carry = incl;
        __syncthreads();
    }
}
__global__ void k_scatter(const int* __restrict__ ei) {
    int e = blockIdx.x * blockDim.x + threadIdx.x;
    if (e < NE) {
        int d = ei[NE + e];
        int p = atomicAdd(&g_cursor[d], 1);
        g_col[p] = ei[e];
    }
}

// ---------------- weight split (fp32 -> bf16 hi/lo, transposed to [n][k]) ----------------
__global__ void k_split_w(const float* __restrict__ w_in, const float* __restrict__ gnn_w,
                          const float* __restrict__ gate_w1) {
    int i = blockIdx.x * blockDim.x + threadIdx.x;
    if (i >= WTOT) return;
    float v;
    if (i < 8192) {
        int n = i >> 6, k = i & 63;
        v = w_in[k * 128 + n];
    } else if (i < 106496) {
        int j = i - 8192;
        int l = j >> 15, r = j & 32767;
        int n = r >> 8, k = r & 255;
        v = gnn_w[((l << 8) + k) * 128 + n];
    } else {
        int j = i - 106496;
        int n = j >> 7, k = j & 127;
        v = gate_w1[k * 128 + n];
    }
    __nv_bfloat16 hb = __float2bfloat16(v);
    g_wh[i] = hb;
    g_wl[i] = __float2bfloat16(v - __bfloat162float(hb));
}

// ---------------- wmma GEMM (bf16 hi/lo 3-pass): g_z = A @ B^T (raw) — R13-verbatim ----------------
template <int KD>
__global__ void __launch_bounds__(256)
gemm_wmma(const float* __restrict__ A0, const float* __restrict__ A1,
          int boff, int nrows) {
    __shared__ __align__(16) __nv_bfloat16 As_h[128 * ASTR];
    __shared__ __align__(16) __nv_bfloat16 As_l[128 * ASTR];
    __shared__ __align__(16) __nv_bfloat16 Bs_h[128 * ASTR];
    __shared__ __align__(16) __nv_bfloat16 Bs_l[128 * ASTR];

    const int t = threadIdx.x;
    const int w = t >> 5;
    const int row0 = blockIdx.x * 128;
    constexpr int NCH = KD / 32;
    constexpr int STRIDE = (KD == 64) ? 64 : 128;

    wmma::fragment<wmma::accumulator, 16, 16, 16, float> acc[8];
#pragma unroll
    for (int j = 0; j < 8; j++) wmma::fill_fragment(acc[j], 0.0f);

#pragma unroll
    for (int c = 0; c < NCH; c++) {
#pragma unroll
        for (int q = 0; q < 2; q++) {
            int idx = q * 256 + t;          // 0..511
            int r = idx >> 2, seg = idx & 3;
            const float* src;
            if (KD == 64)
                src = A0 + (size_t)(row0 + r) * 64 + c * 32 + seg * 8;
            else if (KD == 128)
                src = A0 + (size_t)(row0 + r) * 128 + c * 32 + seg * 8;
            else
                src = (c < 4)
                    ? A0 + (size_t)(row0 + r) * STRIDE + c * 32 + seg * 8
                    : A1 + (size_t)(row0 + r) * STRIDE + (c - 4) * 32 + seg * 8;
            float4 f0 = make_float4(0.f, 0.f, 0.f, 0.f);
            float4 f1 = make_float4(0.f, 0.f, 0.f, 0.f);
            if (row0 + r < nrows) {
                f0 = *reinterpret_cast<const float4*>(src);
                f1 = *reinterpret_cast<const float4*>(src + 4);
            }
            uint4 vh, vl;
            split2(f0.x, f0.y, vh.x, vl.x);
            split2(f0.z, f0.w, vh.y, vl.y);
            split2(f1.x, f1.y, vh.z, vl.z);
            split2(f1.z, f1.w, vh.w, vl.w);
            *reinterpret_cast<uint4*>(As_h + r * ASTR + seg * 8) = vh;
            *reinterpret_cast<uint4*>(As_l + r * ASTR + seg * 8) = vl;
            const size_t wb = (size_t)boff + (size_t)r * KD + c * 32 + seg * 8;
            *reinterpret_cast<uint4*>(Bs_h + r * ASTR + seg * 8) =
                *reinterpret_cast<const uint4*>(g_wh + wb);
            *reinterpret_cast<uint4*>(Bs_l + r * ASTR + seg * 8) =
                *reinterpret_cast<const uint4*>(g_wl + wb);
        }
        __syncthreads();
#pragma unroll
        for (int kk = 0; kk < 32; kk += 16) {
            wmma::fragment<wmma::matrix_a, 16, 16, 16, __nv_bfloat16, wmma::row_major> aH, aL;
            wmma::load_matrix_sync(aH, As_h + w * 16 * ASTR + kk, ASTR);
            wmma::load_matrix_sync(aL, As_l + w * 16 * ASTR + kk, ASTR);
#pragma unroll
            for (int j = 0; j < 8; j++) {
                wmma::fragment<wmma::matrix_b, 16, 16, 16, __nv_bfloat16, wmma::col_major> bH, bL;
                wmma::load_matrix_sync(bH, Bs_h + j * 16 * ASTR + kk, ASTR);
                wmma::load_matrix_sync(bL, Bs_l + j * 16 * ASTR + kk, ASTR);
                wmma::mma_sync(acc[j], aH, bH, acc[j]);
                wmma::mma_sync(acc[j], aL, bH, acc[j]);
                wmma::mma_sync(acc[j], aH, bL, acc[j]);
            }
        }
        __syncthreads();
    }

#pragma unroll
    for (int j = 0; j < 8; j++)
        wmma::store_matrix_sync(g_z + (size_t)(row0 + w * 16) * 128 + j * 16,
                                acc[j], 128, wmma::mem_row_major);
}

// ---------------- elementwise: h = gelu(ln(z + bias)) -> g_h + g_hh ----------------
__global__ void k_ln_gelu(const float* __restrict__ bias, const float* __restrict__ g,
                          const float* __restrict__ b) {
    int gid = blockIdx.x * blockDim.x + threadIdx.x;
    int node = gid >> 5, lane = gid & 31;
    if (node >= NN) return;
    float4 z = *reinterpret_cast<const float4*>(g_z + (size_t)node * DD + lane * 4);
    float4 bv = *reinterpret_cast<const float4*>(bias + lane * 4);
    z.x += bv.x; z.y += bv.y; z.z += bv.z; z.w += bv.w;
    float4 u = ln128(z, g, b, lane);
    u.x = geluf(u.x); u.y = geluf(u.y); u.z = geluf(u.z); u.w = geluf(u.w);
    store_h_pair(u, node, lane);
}

// ---------------- aggregation: mean over CSR neighbors (fp16 gather, MLP x4) ----------------
__global__ void k_aggregate() {
    int gid = blockIdx.x * blockDim.x + threadIdx.x;
    int node = gid >> 5, lane = gid & 31;
    if (node >= NN) return;
    int s = g_rowptr[node], e = g_rowptr[node + 1];
    const uint2* hh = reinterpret_cast<const uint2*>(g_hh);
    float4 a0 = make_float4(0.f, 0.f, 0.f, 0.f);
    float4 a1 = make_float4(0.f, 0.f, 0.f, 0.f);
    float4 a2 = make_float4(0.f, 0.f, 0.f, 0.f);
    float4 a3 = make_float4(0.f, 0.f, 0.f, 0.f);
    int i = s;
    for (; i + 4 <= e; i += 4) {
        int c0 = g_col[i], c1 = g_col[i + 1], c2 = g_col[i + 2], c3 = g_col[i + 3];
        uint2 v0 = hh[(size_t)c0 * 32 + lane];
        uint2 v1 = hh[(size_t)c1 * 32 + lane];
        uint2 v2 = hh[(size_t)c2 * 32 + lane];
        uint2 v3 = hh[(size_t)c3 * 32 + lane];
        acc_h2(a0, v0);
        acc_h2(a1, v1);
        acc_h2(a2, v2);
        acc_h2(a3, v3);
    }
    for (; i < e; i++) {
        uint2 v0 = hh[(size_t)g_col[i] * 32 + lane];
        acc_h2(a0, v0);
    }
    a0.x += a1.x + a2.x + a3.x;
    a0.y += a1.y + a2.y + a3.y;
    a0.z += a1.z + a2.z + a3.z;
    a0.w += a1.w + a2.w + a3.w;
    float inv = 1.0f / g_deg[node];
    a0.x *= inv; a0.y *= inv; a0.z *= inv; a0.w *= inv;
    *reinterpret_cast<float4*>(g_agg + (size_t)node * DD + lane * 4) = a0;
}

// ---------------- per-layer post: gelu(z+bias) -> LN -> LN [-> gelu + residual] ----------------
__global__ void k_layer_post(const float* __restrict__ bias,
                             const float* __restrict__ g1, const float* __restrict__ b1,
                             const float* __restrict__ g2, const float* __restrict__ b2,
                             int residual, float* __restrict__ out_h) {
    int gid = blockIdx.x * blockDim.x + threadIdx.x;
    int node = gid >> 5, lane = gid & 31;
    if (node >= NN) return;
    float4 z = *reinterpret_cast<const float4*>(g_z + (size_t)node * DD + lane * 4);
    float4 bv = *reinterpret_cast<const float4*>(bias + lane * 4);
    float4 t = make_float4(geluf(z.x + bv.x), geluf(z.y + bv.y),
                           geluf(z.z + bv.z), geluf(z.w + bv.w));
    float4 u = ln128(t, g1, b1, lane);
    float4 w = ln128(u, g2, b2, lane);
    float4 r = w;
    if (residual) {
        float4 ho = *reinterpret_cast<const float4*>(g_h + (size_t)node * DD + lane * 4);
        r.x = geluf(w.x) + ho.x;
        r.y = geluf(w.y) + ho.y;
        r.z = geluf(w.z) + ho.z;
        r.w = geluf(w.w) + ho.w;
    }
    store_h_pair(r, node, lane);
    if (out_h)
        *reinterpret_cast<float4*>(out_h + (size_t)node * DD + lane * 4) = r;
}

// ---------------- gate logits: dot(tanh(z + b1), w2) + b2 ----------------
__global__ void k_logits(const float* __restrict__ b1, const float* __restrict__ w2,
                         const float* __restrict__ b2) {
    int gid = blockIdx.x * blockDim.x + threadIdx.x;
    int node = gid >> 5, lane = gid & 31;
    if (node >= NN) return;
    float4 h4 = reinterpret_cast<const float4*>(g_z)[(size_t)node * 32 + lane];
    float4 bv = *reinterpret_cast<const float4*>(b1 + lane * 4);
    float4 w4 = reinterpret_cast<const float4*>(w2)[lane];
    float p = tanhf(h4.x + bv.x) * w4.x + tanhf(h4.y + bv.y) * w4.y +
              tanhf(h4.z + bv.z) * w4.z + tanhf(h4.w + bv.w) * w4.w;
    p = wsum(p);
    if (lane == 0) g_logit[node] = p + b2[0];
}

// ---------------- softmax sum (logits bounded: no max pass) ----------------
__global__ void k_rsum() {
    float s = 0.f;
    for (int i = blockIdx.x * 256 + threadIdx.x; i < NN; i += 256 * 256)
        s += expf(g_logit[i]);
    s = wsum(s);
    __shared__ float sm[8];
    if ((threadIdx.x & 31) == 0) sm[threadIdx.x >> 5] = s;
    __syncthreads();
    if (threadIdx.x == 0) {
        float r = 0.f;
        for (int w = 0; w < 8; w++) r += sm[w];
        g_red[blockIdx.x] = r;
    }
}
__global__ void k_rsum_fin(const int* __restrict__ batch) {
    int t = threadIdx.x;
    float s = g_red[t];
    s = wsum(s);
    __shared__ float sm[8];
    if ((t & 31) == 0) sm[t >> 5] = s;
    __syncthreads();
    if (t == 0) {
        float r = 0.f;
        for (int w = 0; w < 8; w++) r += sm[w];
        g_consts[1] = 1.0f / r;
    }
    if (t <= NB) {
        int lo = 0, hi = NN;
        while (lo < hi) {
            int mid = (lo + hi) >> 1;
            if (batch[mid] < t) lo = mid + 1; else hi = mid;
        }
        g_bstart[t] = lo;
    }
}

// ---------------- pooling (gate inline) ----------------
__global__ void k_pool(float* __restrict__ out_gate) {
    int b = blockIdx.x / POOL_C;
    int c = blockIdx.x % POOL_C;
    int s = g_bstart[b], e = g_bstart[b + 1];
    long long len = e - s;
    int cs = s + (int)(len * c / POOL_C);
    int ce = s + (int)(len * (c + 1) / POOL_C);
    int d = threadIdx.x;
    float inv = g_consts[1];
    float acc = 0.f;
    for (int n = cs; n < ce; n++) {
        float gv = expf(g_logit[n]) * inv;
        acc += gv * g_h[(size_t)n * DD + d];
        if (d == 0 && out_gate) out_gate[n] = gv;
    }
    g_pool_part[((size_t)b * POOL_C + c) * DD + d] = acc;
}
__global__ void k_pool_red() {
    int b = blockIdx.x, d = threadIdx.x;
    float s = 0.f;
    for (int c = 0; c < POOL_C; c++) s += g_pool_part[((size_t)b * POOL_C + c) * DD + d];
    g_pooled[b * DD + d] = s;
}

// ---------------- final out proj ----------------
__global__ void k_out(const float* __restrict__ W, const float* __restrict__ bias,
                      const float* __restrict__ lg, const float* __restrict__ lb,
                      float* __restrict__ outp) {
    __shared__ float sp[NB * DD];
    __shared__ float sz[NB * DD];
    int t = threadIdx.x;
#pragma unroll
    for (int j = 0; j < 4; j++) sp[t + 256 * j] = g_pooled[t + 256 * j];
    __syncthreads();
    int d = t & 127;
    int b0 = t >> 7;
    float acc[4];
#pragma unroll
    for (int j = 0; j < 4; j++) acc[j] = bias[d];
    for (int k = 0; k < DD; k++) {
        float wv = W[k * DD + d];
#pragma unroll
        for (int j = 0; j < 4; j++) acc[j] += sp[(b0 + 2 * j) * DD + k] * wv;
    }
#pragma unroll
    for (int j = 0; j < 4; j++) sz[(b0 + 2 * j) * DD + d] = acc[j];
    __syncthreads();
    int warp = t >> 5, lane = t & 31;
    float4 v = *reinterpret_cast<float4*>(&sz[warp * DD + lane * 4]);
    float4 u = ln128(v, lg, lb, lane);
    outp[warp * DD + lane * 4 + 0] = geluf(u.x);
    outp[warp * DD + lane * 4 + 1] = geluf(u.y);
    outp[warp * DD + lane * 4 + 2] = geluf(u.z);
    outp[warp * DD + lane * 4 + 3] = geluf(u.w);
}

// ---------------- launch ----------------
extern "C" void kernel_launch(void* const* d_in, const int* in_sizes, int n_in,
                              void* d_out, int out_size) {
    const float* x        = (const float*)d_in[0];
    const int*   ei       = (const int*)d_in[1];
    const int*   batch    = (const int*)d_in[2];
    const float* w_in     = (const float*)d_in[3];
    const float* b_in     = (const float*)d_in[4];
    const float* ln_in_g  = (const float*)d_in[5];
    const float* ln_in_b  = (const float*)d_in[6];
    const float* gnn_w    = (const float*)d_in[7];
    const float* gnn_b    = (const float*)d_in[8];
    const float* gnn_ln_g = (const float*)d_in[9];
    const float* gnn_ln_b = (const float*)d_in[10];
    const float* norm_g   = (const float*)d_in[11];
    const float* norm_b   = (const float*)d_in[12];
    const float* gate_w1  = (const float*)d_in[13];
    const float* gate_b1  = (const float*)d_in[14];
    const float* gate_w2  = (const float*)d_in[15];
    const float* gate_b2  = (const float*)d_in[16];
    const float* out_w    = (const float*)d_in[17];
    const float* out_b    = (const float*)d_in[18];
    const float* out_ln_g = (const float*)d_in[19];
    const float* out_ln_b = (const float*)d_in[20];

    float* out = (float*)d_out;
    float* out_h    = (out_size >= NB * DD + NN * DD) ? out + NB * DD : nullptr;
    float* out_gate = (out_size >= NB * DD + NN * DD + NN) ? out + NB * DD + NN * DD : nullptr;

    float* p_h = nullptr;
    float* p_agg = nullptr;
    cudaGetSymbolAddress((void**)&p_h, g_h);
    cudaGetSymbolAddress((void**)&p_agg, g_agg);

    const int GT = (NN + 127) / 128;
    const int GW = (NN * 32 + 255) / 256;
    const int GE = (NE + 255) / 256;
    const int GN = (NN + 255) / 256;

    // CSR build
    k_zero<<<GN, 256>>>();
    k_count<<<GE, 256>>>(ei);
    k_scan<<<1, 1024>>>();
    k_scatter<<<GE, 256>>>(ei);

    // weight split
    k_split_w<<<(WTOT + 255) / 256, 256>>>(w_in, gnn_w, gate_w1);

    // input projection (wmma) + LN/GELU (bias folded)
    gemm_wmma<64><<<GT, 256>>>(x, nullptr, 0, NN);
    k_ln_gelu<<<GW, 256>>>(b_in, ln_in_g, ln_in_b);

    // GNN layers
    for (int l = 0; l < NL; l++) {
        k_aggregate<<<GW, 256>>>();
        gemm_wmma<256><<<GT, 256>>>(p_h, p_agg, 8192 + l * 32768, NN);
        k_layer_post<<<GW, 256>>>(gnn_b + l * 128,
                                  gnn_ln_g + l * 128, gnn_ln_b + l * 128,
                                  norm_g + l * 128, norm_b + l * 128,
                                  (l < NL - 1) ? 1 : 0,
                                  (l == NL - 1) ? out_h : nullptr);
    }

    // gate
    gemm_wmma<128><<<GT, 256>>>(p_h, nullptr, 106496, NN);
    k_logits<<<GW, 256>>>(gate_b1, gate_w2, gate_b2);

    // softmax sum + batch bounds
    k_rsum<<<256, 256>>>();
    k_rsum_fin<<<1, 256>>>(batch);

    // pooling (gate inline)
    k_pool<<<NB * POOL_C, 128>>>(out_gate);
    k_pool_red<<<NB, 128>>>();

    // final projection
    k_out<<<1, 256>>>(out_w, out_b, out_ln_g, out_ln_b, out);
}

// round 17
// speedup vs baseline: 1.1762x; 1.1762x over previous
#include <cuda_runtime.h>
#include <cuda_bf16.h>
#include <cuda_fp16.h>
#include <mma.h>
#include <math.h>
#include <stdint.h>

#define NN 50000
#define NNP 50048         // padded rows for tile-overrun stores
#define NE 800000
#define FIN 64
#define DD 128
#define NL 3
#define NB 8
#define POOL_C 64
#define NBLK 196          // ceil(NN/256)
#define WTOT 122880       // 128*64 + 3*128*256 + 128*128
#define ASTR 40           // smem leading dim (elems): 32 K + 8 pad

using namespace nvcuda;

// ---------------- scratch (device globals; no allocation) ----------------
__device__ __align__(16) float g_h[NN * DD];
__device__ __align__(16) __half g_hh[NN * DD];       // fp16 copy for gathers
__device__ __align__(16) float g_z[NNP * DD];        // padded
__device__ __align__(16) float g_agg[NN * DD];
__device__ __align__(16) __nv_bfloat16 g_wh[WTOT];   // weights [n][k], bf16 hi
__device__ __align__(16) __nv_bfloat16 g_wl[WTOT];   // bf16 lo
__device__ int   g_cnt[NN];
__device__ int   g_inc[NBLK * 256];
__device__ int   g_blksum[NBLK];
__device__ int   g_rowptr[NN + 1];
__device__ int   g_cursor[NN];
__device__ int   g_col[NE];
__device__ float g_deg[NN];
__device__ float g_logit[NN];
__device__ float g_red[256];
__device__ float g_consts[2];
__device__ int   g_bstart[NB + 1];
__device__ float g_pool_part[NB * POOL_C * DD];
__device__ float g_pooled[NB * DD];

// ---------------- helpers ----------------
__device__ __forceinline__ float geluf(float x) {
    return 0.5f * x * (1.0f + erff(x * 0.7071067811865476f));
}
__device__ __forceinline__ float wsum(float v) {
#pragma unroll
    for (int o = 16; o > 0; o >>= 1) v += __shfl_xor_sync(0xffffffffu, v, o);
    return v;
}
__device__ __forceinline__ int wsumi(int v) {
#pragma unroll
    for (int o = 16; o > 0; o >>= 1) v += __shfl_xor_sync(0xffffffffu, v, o);
    return v;
}
__device__ __forceinline__ float4 ln128(float4 v, const float* __restrict__ g,
                                        const float* __restrict__ b, int lane) {
    float m = wsum(v.x + v.y + v.z + v.w) * (1.0f / 128.0f);
    float dx = v.x - m, dy = v.y - m, dz = v.z - m, dw = v.w - m;
    float var = wsum(dx * dx + dy * dy + dz * dz + dw * dw) * (1.0f / 128.0f);
    float rs = rsqrtf(var + 1e-5f);
    float4 gg = *reinterpret_cast<const float4*>(g + lane * 4);
    float4 bb = *reinterpret_cast<const float4*>(b + lane * 4);
    return make_float4(dx * rs * gg.x + bb.x, dy * rs * gg.y + bb.y,
                       dz * rs * gg.z + bb.z, dw * rs * gg.w + bb.w);
}
__device__ __forceinline__ void split2(float a, float b, uint32_t& hi, uint32_t& lo) {
    __nv_bfloat16 ha = __float2bfloat16(a), hb = __float2bfloat16(b);
    __nv_bfloat162 th; th.x = ha; th.y = hb;
    hi = *reinterpret_cast<uint32_t*>(&th);
    __nv_bfloat162 tl;
    tl.x = __float2bfloat16(a - __bfloat162float(ha));
    tl.y = __float2bfloat16(b - __bfloat162float(hb));
    lo = *reinterpret_cast<uint32_t*>(&tl);
}
__device__ __forceinline__ void store_h_pair(float4 r, int row, int lane) {
    *reinterpret_cast<float4*>(g_h + (size_t)row * DD + lane * 4) = r;
    __half2 h0 = __floats2half2_rn(r.x, r.y);
    __half2 h1 = __floats2half2_rn(r.z, r.w);
    uint2 hp = make_uint2(*reinterpret_cast<uint32_t*>(&h0),
                          *reinterpret_cast<uint32_t*>(&h1));
    *reinterpret_cast<uint2*>(g_hh + (size_t)row * DD + lane * 4) = hp;
}

// ---------------- CSR build (multi-block scan) ----------------
__global__ void k_zero() {
    int i = blockIdx.x * blockDim.x + threadIdx.x;
    if (i < NN) g_cnt[i] = 0;
}
__global__ void k_count(const int* __restrict__ ei) {
    int e = blockIdx.x * blockDim.x + threadIdx.x;
    if (e < NE) atomicAdd(&g_cnt[ei[NE + e]], 1);
}
__global__ void k_scan1() {
    __shared__ int sw_[8];
    int b = blockIdx.x, t = threadIdx.x, i = b * 256 + t;
    int v = (i < NN) ? g_cnt[i] : 0;
    int x = v;
#pragma unroll
    for (int o = 1; o < 32; o <<= 1) {
        int y = __shfl_up_sync(0xffffffffu, x, o);
        if ((t & 31) >= o) x += y;
    }
    if ((t & 31) == 31) sw_[t >> 5] = x;
    __syncthreads();
    if (t == 0) {
        int s = 0;
        for (int w = 0; w < 8; w++) { int tmp = sw_[w]; sw_[w] = s; s += tmp; }
    }
    __syncthreads();
    int incl = x + sw_[t >> 5];
    g_inc[b * 256 + t] = incl;
    if (t == 255) g_blksum[b] = incl;
}
__global__ void k_scan3() {
    __shared__ int soff;
    int blk = blockIdx.x, t = threadIdx.x;
    if (t < 32) {
        int s = 0;
        for (int b = t; b < blk; b += 32) s += g_blksum[b];
        s = wsumi(s);
        if (t == 0) soff = s;
    }
    __syncthreads();
    int i = blk * 256 + t;
    if (i >= NN) return;
    int incl = g_inc[i] + soff;
    int v = g_cnt[i];
    g_rowptr[i + 1] = incl;
    g_cursor[i] = incl - v;
    g_deg[i] = (v > 0) ? (float)v : 1.0f;
    if (i == 0) g_rowptr[0] = 0;
}
__global__ void k_scatter(const int* __restrict__ ei) {
    int e = blockIdx.x * blockDim.x + threadIdx.x;
    if (e < NE) {
        int d = ei[NE + e];
        int p = atomicAdd(&g_cursor[d], 1);
        g_col[p] = ei[e];
    }
}

// ---------------- weight split (fp32 -> bf16 hi/lo, transposed to [n][k]) ----------------
__global__ void k_split_w(const float* __restrict__ w_in, const float* __restrict__ gnn_w,
                          const float* __restrict__ gate_w1) {
    int i = blockIdx.x * blockDim.x + threadIdx.x;
    if (i >= WTOT) return;
    float v;
    if (i < 8192) {
        int n = i >> 6, k = i & 63;
        v = w_in[k * 128 + n];
    } else if (i < 106496) {
        int j = i - 8192;
        int l = j >> 15, r = j & 32767;
        int n = r >> 8, k = r & 255;
        v = gnn_w[((l << 8) + k) * 128 + n];
    } else {
        int j = i - 106496;
        int n = j >> 7, k = j & 127;
        v = gate_w1[k * 128 + n];
    }
    __nv_bfloat16 hb = __float2bfloat16(v);
    g_wh[i] = hb;
    g_wl[i] = __float2bfloat16(v - __bfloat162float(hb));
}

// ---------------- wmma GEMM (bf16 hi/lo 3-pass, 4x2 warp tiling): g_z = A @ B^T ----------------
template <int KD>
__global__ void __launch_bounds__(256)
gemm_wmma(const float* __restrict__ A0, const float* __restrict__ A1,
          int boff, int nrows) {
    __shared__ __align__(16) __nv_bfloat16 As_h[128 * ASTR];
    __shared__ __align__(16) __nv_bfloat16 As_l[128 * ASTR];
    __shared__ __align__(16) __nv_bfloat16 Bs_h[128 * ASTR];
    __shared__ __align__(16) __nv_bfloat16 Bs_l[128 * ASTR];

    const int t = threadIdx.x;
    const int w = t >> 5;
    const int wr = w >> 1, wc = w & 1;   // warp covers rows [wr*32, +32), cols [wc*64, +64)
    const int row0 = blockIdx.x * 128;
    constexpr int NCH = KD / 32;
    constexpr int STRIDE = (KD == 64) ? 64 : 128;

    wmma::fragment<wmma::accumulator, 16, 16, 16, float> acc[2][4];
#pragma unroll
    for (int i = 0; i < 2; i++)
#pragma unroll
        for (int j = 0; j < 4; j++) wmma::fill_fragment(acc[i][j], 0.0f);

#pragma unroll
    for (int c = 0; c < NCH; c++) {
#pragma unroll
        for (int q = 0; q < 2; q++) {
            int idx = q * 256 + t;          // 0..511
            int r = idx >> 2, seg = idx & 3;
            const float* src;
            if (KD == 64)
                src = A0 + (size_t)(row0 + r) * 64 + c * 32 + seg * 8;
            else if (KD == 128)
                src = A0 + (size_t)(row0 + r) * 128 + c * 32 + seg * 8;
            else
                src = (c < 4)
                    ? A0 + (size_t)(row0 + r) * STRIDE + c * 32 + seg * 8
                    : A1 + (size_t)(row0 + r) * STRIDE + (c - 4) * 32 + seg * 8;
            float4 f0 = make_float4(0.f, 0.f, 0.f, 0.f);
            float4 f1 = make_float4(0.f, 0.f, 0.f, 0.f);
            if (row0 + r < nrows) {
                f0 = *reinterpret_cast<const float4*>(src);
                f1 = *reinterpret_cast<const float4*>(src + 4);
            }
            uint4 vh, vl;
            split2(f0.x, f0.y, vh.x, vl.x);
            split2(f0.z, f0.w, vh.y, vl.y);
            split2(f1.x, f1.y, vh.z, vl.z);
            split2(f1.z, f1.w, vh.w, vl.w);
            *reinterpret_cast<uint4*>(As_h + r * ASTR + seg * 8) = vh;
            *reinterpret_cast<uint4*>(As_l + r * ASTR + seg * 8) = vl;
            const size_t wb = (size_t)boff + (size_t)r * KD + c * 32 + seg * 8;
            *reinterpret_cast<uint4*>(Bs_h + r * ASTR + seg * 8) =
                *reinterpret_cast<const uint4*>(g_wh + wb);
            *reinterpret_cast<uint4*>(Bs_l + r * ASTR + seg * 8) =
                *reinterpret_cast<const uint4*>(g_wl + wb);
        }
        __syncthreads();
#pragma unroll
        for (int kk = 0; kk < 32; kk += 16) {
            wmma::fragment<wmma::matrix_b, 16, 16, 16, __nv_bfloat16, wmma::col_major> bH[4], bL[4];
#pragma unroll
            for (int j = 0; j < 4; j++) {
                wmma::load_matrix_sync(bH[j], Bs_h + (wc * 64 + j * 16) * ASTR + kk, ASTR);
                wmma::load_matrix_sync(bL[j], Bs_l + (wc * 64 + j * 16) * ASTR + kk, ASTR);
            }
#pragma unroll
            for (int i = 0; i < 2; i++) {
                wmma::fragment<wmma::matrix_a, 16, 16, 16, __nv_bfloat16, wmma::row_major> aH, aL;
                wmma::load_matrix_sync(aH, As_h + (wr * 32 + i * 16) * ASTR + kk, ASTR);
                wmma::load_matrix_sync(aL, As_l + (wr * 32 + i * 16) * ASTR + kk, ASTR);
#pragma unroll
                for (int j = 0; j < 4; j++) {
                    wmma::mma_sync(acc[i][j], aH, bH[j], acc[i][j]);
                    wmma::mma_sync(acc[i][j], aL, bH[j], acc[i][j]);
                    wmma::mma_sync(acc[i][j], aH, bL[j], acc[i][j]);
                }
            }
        }
        __syncthreads();
    }

#pragma unroll
    for (int i = 0; i < 2; i++)
#pragma unroll
        for (int j = 0; j < 4; j++)
            wmma::store_matrix_sync(g_z + (size_t)(row0 + wr * 32 + i * 16) * 128 +
                                        wc * 64 + j * 16,
                                    acc[i][j], 128, wmma::mem_row_major);
}

// ---------------- elementwise: h = gelu(ln(z + bias)) -> g_h + g_hh ----------------
__global__ void k_ln_gelu(const float* __restrict__ bias, const float* __restrict__ g,
                          const float* __restrict__ b) {
    int gid = blockIdx.x * blockDim.x + threadIdx.x;
    int node = gid >> 5, lane = gid & 31;
    if (node >= NN) return;
    float4 z = *reinterpret_cast<const float4*>(g_z + (size_t)node * DD + lane * 4);
    float4 bv = *reinterpret_cast<const float4*>(bias + lane * 4);
    z.x += bv.x; z.y += bv.y; z.z += bv.z; z.w += bv.w;
    float4 u = ln128(z, g, b, lane);
    u.x = geluf(u.x); u.y = geluf(u.y); u.z = geluf(u.z); u.w = geluf(u.w);
    store_h_pair(u, node, lane);
}

// ---------------- aggregation: mean over CSR neighbors (fp16 gather) ----------------
__global__ void k_aggregate() {
    int gid = blockIdx.x * blockDim.x + threadIdx.x;
    int node = gid >> 5, lane = gid & 31;
    if (node >= NN) return;
    int s = g_rowptr[node], e = g_rowptr[node + 1];
    float4 acc = make_float4(0.f, 0.f, 0.f, 0.f);
    const uint2* hh = reinterpret_cast<const uint2*>(g_hh);
    for (int i = s; i < e; i++) {
        int src = g_col[i];
        uint2 v = hh[(size_t)src * 32 + lane];
        float2 f0 = __half22float2(*reinterpret_cast<__half2*>(&v.x));
        float2 f1 = __half22float2(*reinterpret_cast<__half2*>(&v.y));
        acc.x += f0.x; acc.y += f0.y; acc.z += f1.x; acc.w += f1.y;
    }
    float inv = 1.0f / g_deg[node];
    acc.x *= inv; acc.y *= inv; acc.z *= inv; acc.w *= inv;
    *reinterpret_cast<float4*>(g_agg + (size_t)node * DD + lane * 4) = acc;
}

// ---------------- per-layer post: gelu(z+bias) -> LN -> LN [-> gelu + residual] ----------------
__global__ void k_layer_post(const float* __restrict__ bias,
                             const float* __restrict__ g1, const float* __restrict__ b1,
                             const float* __restrict__ g2, const float* __restrict__ b2,
                             int residual, float* __restrict__ out_h) {
    int gid = blockIdx.x * blockDim.x + threadIdx.x;
    int node = gid >> 5, lane = gid & 31;
    if (node >= NN) return;
    float4 z = *reinterpret_cast<const float4*>(g_z + (size_t)node * DD + lane * 4);
    float4 bv = *reinterpret_cast<const float4*>(bias + lane * 4);
    float4 t = make_float4(geluf(z.x + bv.x), geluf(z.y + bv.y),
                           geluf(z.z + bv.z), geluf(z.w + bv.w));
    float4 u = ln128(t, g1, b1, lane);
    float4 w = ln128(u, g2, b2, lane);
    float4 r = w;
    if (residual) {
        float4 ho = *reinterpret_cast<const float4*>(g_h + (size_t)node * DD + lane * 4);
        r.x = geluf(w.x) + ho.x;
        r.y = geluf(w.y) + ho.y;
        r.z = geluf(w.z) + ho.z;
        r.w = geluf(w.w) + ho.w;
    }
    store_h_pair(r, node, lane);
    if (out_h)
        *reinterpret_cast<float4*>(out_h + (size_t)node * DD + lane * 4) = r;
}

// ---------------- gate logits: dot(tanh(z + b1), w2) + b2 ----------------
__global__ void k_logits(const float* __restrict__ b1, const float* __restrict__ w2,
                         const float* __restrict__ b2) {
    int gid = blockIdx.x * blockDim.x + threadIdx.x;
    int node = gid >> 5, lane = gid & 31;
    if (node >= NN) return;
    float4 h4 = reinterpret_cast<const float4*>(g_z)[(size_t)node * 32 + lane];
    float4 bv = *reinterpret_cast<const float4*>(b1 + lane * 4);
    float4 w4 = reinterpret_cast<const float4*>(w2)[lane];
    float p = tanhf(h4.x + bv.x) * w4.x + tanhf(h4.y + bv.y) * w4.y +
              tanhf(h4.z + bv.z) * w4.z + tanhf(h4.w + bv.w) * w4.w;
    p = wsum(p);
    if (lane == 0) g_logit[node] = p + b2[0];
}

// ---------------- softmax sum (logits bounded: no max pass) ----------------
__global__ void k_rsum() {
    float s = 0.f;
    for (int i = blockIdx.x * 256 + threadIdx.x; i < NN; i += 256 * 256)
        s += expf(g_logit[i]);
    s = wsum(s);
    __shared__ float sm[8];
    if ((threadIdx.x & 31) == 0) sm[threadIdx.x >> 5] = s;
    __syncthreads();
    if (threadIdx.x == 0) {
        float r = 0.f;
        for (int w = 0; w < 8; w++) r += sm[w];
        g_red[blockIdx.x] = r;
    }
}
__global__ void k_rsum_fin(const int* __restrict__ batch) {
    int t = threadIdx.x;
    float s = g_red[t];
    s = wsum(s);
    __shared__ float sm[8];
    if ((t & 31) == 0) sm[t >> 5] = s;
    __syncthreads();
    if (t == 0) {
        float r = 0.f;
        for (int w = 0; w < 8; w++) r += sm[w];
        g_consts[1] = 1.0f / r;
    }
    if (t <= NB) {
        int lo = 0, hi = NN;
        while (lo < hi) {
            int mid = (lo + hi) >> 1;
            if (batch[mid] < t) lo = mid + 1; else hi = mid;
        }
        g_bstart[t] = lo;
    }
}

// ---------------- pooling (gate inline) ----------------
__global__ void k_pool(float* __restrict__ out_gate) {
    int b = blockIdx.x / POOL_C;
    int c = blockIdx.x % POOL_C;
    int s = g_bstart[b], e = g_bstart[b + 1];
    long long len = e - s;
    int cs = s + (int)(len * c / POOL_C);
    int ce = s + (int)(len * (c + 1) / POOL_C);
    int d = threadIdx.x;
    float inv = g_consts[1];
    float acc = 0.f;
    for (int n = cs; n < ce; n++) {
        float gv = expf(g_logit[n]) * inv;
        acc += gv * g_h[(size_t)n * DD + d];
        if (d == 0 && out_gate) out_gate[n] = gv;
    }
    g_pool_part[((size_t)b * POOL_C + c) * DD + d] = acc;
}
__global__ void k_pool_red() {
    int b = blockIdx.x, d = threadIdx.x;
    float s = 0.f;
    for (int c = 0; c < POOL_C; c++) s += g_pool_part[((size_t)b * POOL_C + c) * DD + d];
    g_pooled[b * DD + d] = s;
}

// ---------------- final out proj ----------------
__global__ void k_out(const float* __restrict__ W, const float* __restrict__ bias,
                      const float* __restrict__ lg, const float* __restrict__ lb,
                      float* __restrict__ outp) {
    __shared__ float sp[NB * DD];
    __shared__ float sz[NB * DD];
    int t = threadIdx.x;
#pragma unroll
    for (int j = 0; j < 4; j++) sp[t + 256 * j] = g_pooled[t + 256 * j];
    __syncthreads();
    int d = t & 127;
    int b0 = t >> 7;
    float acc[4];
#pragma unroll
    for (int j = 0; j < 4; j++) acc[j] = bias[d];
    for (int k = 0; k < DD; k++) {
        float wv = W[k * DD + d];
#pragma unroll
        for (int j = 0; j < 4; j++) acc[j] += sp[(b0 + 2 * j) * DD + k] * wv;
    }
#pragma unroll
    for (int j = 0; j < 4; j++) sz[(b0 + 2 * j) * DD + d] = acc[j];
    __syncthreads();
    int warp = t >> 5, lane = t & 31;
    float4 v = *reinterpret_cast<float4*>(&sz[warp * DD + lane * 4]);
    float4 u = ln128(v, lg, lb, lane);
    outp[warp * DD + lane * 4 + 0] = geluf(u.x);
    outp[warp * DD + lane * 4 + 1] = geluf(u.y);
    outp[warp * DD + lane * 4 + 2] = geluf(u.z);
    outp[warp * DD + lane * 4 + 3] = geluf(u.w);
}

// ---------------- launch ----------------
extern "C" void kernel_launch(void* const* d_in, const int* in_sizes, int n_in,
                              void* d_out, int out_size) {
    const float* x        = (const float*)d_in[0];
    const int*   ei       = (const int*)d_in[1];
    const int*   batch    = (const int*)d_in[2];
    const float* w_in     = (const float*)d_in[3];
    const float* b_in     = (const float*)d_in[4];
    const float* ln_in_g  = (const float*)d_in[5];
    const float* ln_in_b  = (const float*)d_in[6];
    const float* gnn_w    = (const float*)d_in[7];
    const float* gnn_b    = (const float*)d_in[8];
    const float* gnn_ln_g = (const float*)d_in[9];
    const float* gnn_ln_b = (const float*)d_in[10];
    const float* norm_g   = (const float*)d_in[11];
    const float* norm_b   = (const float*)d_in[12];
    const float* gate_w1  = (const float*)d_in[13];
    const float* gate_b1  = (const float*)d_in[14];
    const float* gate_w2  = (const float*)d_in[15];
    const float* gate_b2  = (const float*)d_in[16];
    const float* out_w    = (const float*)d_in[17];
    const float* out_b    = (const float*)d_in[18];
    const float* out_ln_g = (const float*)d_in[19];
    const float* out_ln_b = (const float*)d_in[20];

    float* out = (float*)d_out;
    float* out_h    = (out_size >= NB * DD + NN * DD) ? out + NB * DD : nullptr;
    float* out_gate = (out_size >= NB * DD + NN * DD + NN) ? out + NB * DD + NN * DD : nullptr;

    float* p_h = nullptr;
    float* p_agg = nullptr;
    cudaGetSymbolAddress((void**)&p_h, g_h);
    cudaGetSymbolAddress((void**)&p_agg, g_agg);

    const int GT = (NN + 127) / 128;
    const int GW = (NN * 32 + 255) / 256;
    const int GE = (NE + 255) / 256;
    const int GN = (NN + 255) / 256;

    // CSR build (multi-block scan)
    k_zero<<<GN, 256>>>();
    k_count<<<GE, 256>>>(ei);
    k_scan1<<<NBLK, 256>>>();
    k_scan3<<<NBLK, 256>>>();
    k_scatter<<<GE, 256>>>(ei);

    // weight split
    k_split_w<<<(WTOT + 255) / 256, 256>>>(w_in, gnn_w, gate_w1);

    // input projection (wmma) + LN/GELU (bias folded)
    gemm_wmma<64><<<GT, 256>>>(x, nullptr, 0, NN);
    k_ln_gelu<<<GW, 256>>>(b_in, ln_in_g, ln_in_b);

    // GNN layers
    for (int l = 0; l < NL; l++) {
        k_aggregate<<<GW, 256>>>();
        gemm_wmma<256><<<GT, 256>>>(p_h, p_agg, 8192 + l * 32768, NN);
        k_layer_post<<<GW, 256>>>(gnn_b + l * 128,
                                  gnn_ln_g + l * 128, gnn_ln_b + l * 128,
                                  norm_g + l * 128, norm_b + l * 128,
                                  (l < NL - 1) ? 1 : 0,
                                  (l == NL - 1) ? out_h : nullptr);
    }

    // gate
    gemm_wmma<128><<<GT, 256>>>(p_h, nullptr, 106496, NN);
    k_logits<<<GW, 256>>>(gate_b1, gate_w2, gate_b2);

    // softmax sum + batch bounds
    k_rsum<<<256, 256>>>();
    k_rsum_fin<<<1, 256>>>(batch);

    // pooling (gate inline)
    k_pool<<<NB * POOL_C, 128>>>(out_gate);
    k_pool_red<<<NB, 128>>>();

    // final projection
    k_out<<<1, 256>>>(out_w, out_b, out_ln_g, out_ln_b, out);
}